// round 3
// baseline (speedup 1.0000x reference)
#include <cuda_runtime.h>
#include <math.h>

#define HH 512
#define WW 512
#define CHW 128
#define FHW 256
#define CF 256
#define NCc 3
#define NPTS 2048
#define NUM_OVER 6144
#define STEP1 1536
#define STEP2 512
#define BB 2
#define FEAT_DIM 259
#define NROWS (BB*NPTS)                    // 4096
#define FINE_FLAT (BB*NPTS*CF)             // 1048576
#define FLAT_TOTAL (FINE_FLAT + BB*NPTS*NCc) // 1060864
#define OUT_OFF (BB*NCc*NPTS)              // 12288
#define MASK_SIZE (BB*HH*WW)               // 524288
#define RPB 16                              // rows per block in MLP

// ---------------- device scratch (no allocations allowed) ----------------
__device__ float g_u[BB*NUM_OVER];
__device__ unsigned char g_sel[BB*NUM_OVER];
__device__ int   g_pts[BB*NPTS];
__device__ float g_flat[FLAT_TOTAL];
__device__ float g_w1t[FEAT_DIM*256];
__device__ float g_w2t[FEAT_DIM*128];

// ---------------- weight transpose (coalesce MLP weight reads) -----------
__global__ void k_wt(const float* __restrict__ w1, const float* __restrict__ w2) {
    int t = blockIdx.x * blockDim.x + threadIdx.x;
    if (t < FEAT_DIM*256) { int o = t / FEAT_DIM, c = t % FEAT_DIM; g_w1t[c*256 + o] = w1[t]; }
    if (t < FEAT_DIM*128) { int o = t / FEAT_DIM, c = t % FEAT_DIM; g_w2t[c*128 + o] = w2[t]; }
}

// ---------------- uncertainty at 6144 candidates x 2 batches -------------
__global__ void k_unc(const float* __restrict__ coarse, const int* __restrict__ rnd) {
    int t = blockIdx.x * blockDim.x + threadIdx.x;
    if (t >= BB*NUM_OVER) return;
    int b = t / NUM_OVER, j = t % NUM_OVER;
    int idx = rnd[j];
    int h = idx / WW, w = idx % WW;
    // 128 -> 512 bilinear: src = i/4 - 0.375 (half-pixel), clamp == jax renorm
    float yc = (float)h * 0.25f - 0.375f;
    float xc = (float)w * 0.25f - 0.375f;
    int y0 = (int)floorf(yc); float fy = yc - (float)y0;
    int x0 = (int)floorf(xc); float fx = xc - (float)x0;
    int y0c = min(max(y0,   0), CHW-1), y1c = min(max(y0+1, 0), CHW-1);
    int x0c = min(max(x0,   0), CHW-1), x1c = min(max(x0+1, 0), CHW-1);
    float p[3];
    const float* base = coarse + (size_t)b * NCc * CHW * CHW;
#pragma unroll
    for (int c = 0; c < 3; c++) {
        const float* pc = base + c * CHW * CHW;
        float v00 = pc[y0c*CHW + x0c], v01 = pc[y0c*CHW + x1c];
        float v10 = pc[y1c*CHW + x0c], v11 = pc[y1c*CHW + x1c];
        float top = v00 * (1.f - fx) + v01 * fx;
        float bot = v10 * (1.f - fx) + v11 * fx;
        p[c] = top * (1.f - fy) + bot * fy;
    }
    float m  = fmaxf(p[0], fmaxf(p[1], p[2]));
    float e0 = expf(p[0]-m), e1 = expf(p[1]-m), e2 = expf(p[2]-m);
    float s  = e0 + e1 + e2;
    float q0 = e0/s, q1 = e1/s, q2 = e2/s;
    float mx  = fmaxf(q0, fmaxf(q1, q2));
    float mn  = fminf(q0, fminf(q1, q2));
    float mid = q0 + q1 + q2 - mx - mn;
    g_u[t] = 1.0f - (mx - mid);
}

// ---------------- rank selection: warp per candidate ---------------------
// selected set == top-k with jax tie-break (value desc, index asc)
__global__ void k_rank() {
    int b    = blockIdx.y;
    int warp = threadIdx.x >> 5, lane = threadIdx.x & 31;
    int j = blockIdx.x * 8 + warp;
    const float* u = g_u + b * NUM_OVER;
    float uj = u[j];
    int cnt = 0;
    for (int k = lane; k < NUM_OVER; k += 32) {
        float uk = u[k];
        cnt += (uk > uj) || (uk == uj && k < j);
    }
#pragma unroll
    for (int o = 16; o; o >>= 1) cnt += __shfl_down_sync(0xFFFFFFFFu, cnt, o);
    if (lane == 0) g_sel[b*NUM_OVER + j] = (cnt < STEP1) ? 1 : 0;
}

// ---------------- compact + append coverage + bitonic sort + mask --------
__global__ void k_build(const int* __restrict__ rnd, float* __restrict__ mask_out) {
    __shared__ int pts[NPTS];
    __shared__ int cnt;
    int b = blockIdx.x;
    if (threadIdx.x == 0) cnt = 0;
    __syncthreads();
    for (int j = threadIdx.x; j < NUM_OVER; j += blockDim.x)
        if (g_sel[b*NUM_OVER + j]) pts[atomicAdd(&cnt, 1)] = rnd[j];   // lin == idx
    for (int i = threadIdx.x; i < STEP2; i += blockDim.x)
        pts[STEP1 + i] = rnd[HH*WW - STEP2 + i];
    __syncthreads();
    // bitonic sort ascending, 2048 elems, 1024 threads
    for (int k = 2; k <= NPTS; k <<= 1) {
        for (int j = k >> 1; j > 0; j >>= 1) {
            for (int i = threadIdx.x; i < NPTS; i += blockDim.x) {
                int ixj = i ^ j;
                if (ixj > i) {
                    int a = pts[i], c = pts[ixj];
                    bool up = ((i & k) == 0);
                    if ((a > c) == up) { pts[i] = c; pts[ixj] = a; }
                }
            }
            __syncthreads();
        }
    }
    for (int i = threadIdx.x; i < NPTS; i += blockDim.x) {
        int lin = pts[i];
        g_pts[b*NPTS + i] = lin;
        mask_out[b*HH*WW + lin] = 1.0f;
    }
}

// ---------------- gather fine(256ch, x2 bilinear) + coarse logits --------
__global__ void k_sample(const float* __restrict__ fine, const float* __restrict__ coarse) {
    __shared__ int   sy0, sy1, sx0, sx1, cy0, cy1, cx0, cx1;
    __shared__ float sfy, sfx, cfy, cfx;
    int g = blockIdx.x;               // 0..4095 (b*2048 + n, sorted order)
    int b = g >> 11;
    if (threadIdx.x == 0) {
        int idx = g_pts[g];
        int h = idx / WW, w = idx % WW;
        // fine: 256 -> 512, src = i/2 - 0.25
        float yf = (float)h * 0.5f - 0.25f;
        float xf = (float)w * 0.5f - 0.25f;
        int y0 = (int)floorf(yf); sfy = yf - (float)y0;
        int x0 = (int)floorf(xf); sfx = xf - (float)x0;
        sy0 = min(max(y0,   0), FHW-1); sy1 = min(max(y0+1, 0), FHW-1);
        sx0 = min(max(x0,   0), FHW-1); sx1 = min(max(x0+1, 0), FHW-1);
        // coarse: 128 -> 512, src = i/4 - 0.375
        float yc = (float)h * 0.25f - 0.375f;
        float xc = (float)w * 0.25f - 0.375f;
        int cy = (int)floorf(yc); cfy = yc - (float)cy;
        int cx = (int)floorf(xc); cfx = xc - (float)cx;
        cy0 = min(max(cy,   0), CHW-1); cy1 = min(max(cy+1, 0), CHW-1);
        cx0 = min(max(cx,   0), CHW-1); cx1 = min(max(cx+1, 0), CHW-1);
    }
    __syncthreads();
    int c = threadIdx.x;              // 256 channels
    {
        const float* pf = fine + ((size_t)b * CF + c) * (FHW * FHW);
        float v00 = pf[sy0*FHW + sx0], v01 = pf[sy0*FHW + sx1];
        float v10 = pf[sy1*FHW + sx0], v11 = pf[sy1*FHW + sx1];
        float top = v00 * (1.f - sfx) + v01 * sfx;
        float bot = v10 * (1.f - sfx) + v11 * sfx;
        g_flat[(size_t)g * CF + c] = top * (1.f - sfy) + bot * sfy;
    }
    if (c < NCc) {
        const float* pc = coarse + ((size_t)b * NCc + c) * (CHW * CHW);
        float v00 = pc[cy0*CHW + cx0], v01 = pc[cy0*CHW + cx1];
        float v10 = pc[cy1*CHW + cx0], v11 = pc[cy1*CHW + cx1];
        float top = v00 * (1.f - cfx) + v01 * cfx;
        float bot = v10 * (1.f - cfx) + v11 * cfx;
        g_flat[FINE_FLAT + (size_t)g * NCc + c] = top * (1.f - cfy) + bot * cfy;
    }
}

// ---------------- MLP, 16 rows per block (16x weight-traffic reuse) ------
// Rows read the SCRAMBLED flat buffer at g*259 exactly like the reference
// reshape does (fine.ravel() ++ coarse.ravel() -> (B, NPTS, 259)).
__global__ __launch_bounds__(256) void k_mlp(const float* __restrict__ w3,
                                             const float* __restrict__ pa,
                                             float* __restrict__ out) {
    __shared__ float xs[RPB][FEAT_DIM];
    __shared__ float l1s[RPB][256];
    __shared__ float l2s[RPB][128];
    int g0 = blockIdx.x * RPB;
    float a = *pa;
    for (int t = threadIdx.x; t < RPB*FEAT_DIM; t += 256) {
        int r = t / FEAT_DIM, c = t % FEAT_DIM;
        xs[r][c] = g_flat[(size_t)(g0 + r) * FEAT_DIM + c];
    }
    __syncthreads();
    // ---- layer 1: 259 -> 256, prelu ----
    int o = threadIdx.x;
    float acc[RPB];
#pragma unroll
    for (int r = 0; r < RPB; r++) acc[r] = 0.f;
    for (int c = 0; c < FEAT_DIM; c++) {
        float wv = g_w1t[c*256 + o];
#pragma unroll
        for (int r = 0; r < RPB; r++) acc[r] = fmaf(wv, xs[r][c], acc[r]);
    }
#pragma unroll
    for (int r = 0; r < RPB; r++) l1s[r][o] = acc[r] >= 0.f ? acc[r] : a * acc[r];
    __syncthreads();
    // ---- layer 2: [l1(256) ++ tail(3)] -> 128, prelu ----
    {
        int o2 = threadIdx.x & 127;
        int r0 = threadIdx.x >> 7;   // 0 or 1; rows r0, r0+2, ...
        float acc2[RPB/2];
#pragma unroll
        for (int rr = 0; rr < RPB/2; rr++) acc2[rr] = 0.f;
        for (int c = 0; c < 256; c++) {
            float wv = g_w2t[c*128 + o2];
#pragma unroll
            for (int rr = 0; rr < RPB/2; rr++)
                acc2[rr] = fmaf(wv, l1s[r0 + 2*rr][c], acc2[rr]);
        }
#pragma unroll
        for (int t = 0; t < 3; t++) {
            float wv = g_w2t[(256 + t)*128 + o2];
#pragma unroll
            for (int rr = 0; rr < RPB/2; rr++)
                acc2[rr] = fmaf(wv, xs[r0 + 2*rr][256 + t], acc2[rr]);
        }
#pragma unroll
        for (int rr = 0; rr < RPB/2; rr++) {
            float v = acc2[rr];
            l2s[r0 + 2*rr][o2] = v >= 0.f ? v : a * v;
        }
    }
    __syncthreads();
    // ---- layer 3: [l2(128) ++ tail(3)] -> 3 ----
    if (threadIdx.x < RPB*NCc) {
        int r = threadIdx.x / 3, oo = threadIdx.x % 3;
        float s = 0.f;
        for (int c = 0; c < 128; c++) s = fmaf(w3[oo*131 + c], l2s[r][c], s);
#pragma unroll
        for (int t = 0; t < 3; t++)  s = fmaf(w3[oo*131 + 128 + t], xs[r][256 + t], s);
        int g = g0 + r;
        int b = g >> 11, n = g & 2047;
        out[(b*NCc + oo)*NPTS + n] = s;
    }
}

// ---------------- launch ----------------
extern "C" void kernel_launch(void* const* d_in, const int* in_sizes, int n_in,
                              void* d_out, int out_size) {
    const float* fine   = (const float*)d_in[0];   // (2,256,256,256)
    const float* coarse = (const float*)d_in[1];   // (2,3,128,128)
    const float* w1     = (const float*)d_in[2];   // (256,259)
    const float* w2     = (const float*)d_in[3];   // (128,259)
    const float* w3     = (const float*)d_in[4];   // (3,131)
    const float* pa     = (const float*)d_in[5];   // scalar
    const int*   rnd    = (const int*)d_in[6];     // (262144,)
    float* out = (float*)d_out;

    k_wt<<<(FEAT_DIM*256 + 255)/256, 256>>>(w1, w2);
    k_unc<<<(BB*NUM_OVER + 255)/256, 256>>>(coarse, rnd);
    cudaMemsetAsync(out + OUT_OFF, 0, (size_t)MASK_SIZE * sizeof(float), 0);
    {
        dim3 grid(NUM_OVER/8, BB);
        k_rank<<<grid, 256>>>();
    }
    k_build<<<BB, 1024>>>(rnd, out + OUT_OFF);
    k_sample<<<NROWS, 256>>>(fine, coarse);
    k_mlp<<<NROWS/RPB, 256>>>(w3, pa, out);
    (void)in_sizes; (void)n_in; (void)out_size;
}